// round 16
// baseline (speedup 1.0000x reference)
#include <cuda_runtime.h>
#include <math.h>

#define SQ    2048
#define NH    12
#define HD    128
#define DM    1536
#define NQB   16
#define NKB   32
#define KSEL  7
#define ATT_SCALE 0.08838834764831845f   // 1/sqrt(128)

// ----------------------------- scratch (device globals; no cudaMalloc) -----
__device__ float g_Qraw[SQ*DM];
__device__ float g_Kraw[SQ*DM];
__device__ float g_Vraw[SQ*DM];
__device__ float g_q [NH*SQ*HD];
__device__ float g_k [NH*SQ*HD];
__device__ float g_v [NH*SQ*HD];
__device__ float g_lq[NH*SQ*HD];
__device__ float g_lk[NH*SQ*HD];
__device__ float g_qbm[NH*NQB*HD];
__device__ float g_kbm[NH*NKB*HD];
__device__ int   g_selbuf[NH*NQB*8];
__device__ float g_Mkv[(size_t)NH*NKB*HD*HD];
__device__ float g_slk[NH*NKB*HD];
__device__ float g_sumM[NH*HD*HD];
__device__ float g_sumsl[NH*HD];
__device__ float g_O[SQ*DM];

// =================== SGEMM: C[M,N] = A[M,K] @ B[K,N] + bias ================
__global__ __launch_bounds__(256) void sgemm_bias(
    const float* __restrict__ A, const float* __restrict__ B,
    const float* __restrict__ bias, float* __restrict__ C,
    int M, int N, int K)
{
    __shared__ float As[16][128];
    __shared__ float Bs[16][128];
    int tid = threadIdx.x;
    int tx = tid & 15, ty = tid >> 4;
    int m0 = blockIdx.y * 128, n0 = blockIdx.x * 128;
    float acc[8][8] = {};
    for (int k0 = 0; k0 < K; k0 += 16) {
#pragma unroll
        for (int it = 0; it < 2; it++) {
            int idx = tid + it * 256;
            int ar = idx >> 2, aq = idx & 3;
            float4 av = *(const float4*)(A + (size_t)(m0 + ar) * K + k0 + aq * 4);
            As[aq*4+0][ar] = av.x; As[aq*4+1][ar] = av.y;
            As[aq*4+2][ar] = av.z; As[aq*4+3][ar] = av.w;
            int bk = idx >> 5, bn = idx & 31;
            *(float4*)&Bs[bk][bn*4] =
                *(const float4*)(B + (size_t)(k0 + bk) * N + n0 + bn * 4);
        }
        __syncthreads();
#pragma unroll
        for (int k = 0; k < 16; k++) {
            float a[8], b[8];
            *(float4*)(a)     = *(float4*)&As[k][ty*8];
            *(float4*)(a + 4) = *(float4*)&As[k][ty*8 + 4];
            *(float4*)(b)     = *(float4*)&Bs[k][tx*8];
            *(float4*)(b + 4) = *(float4*)&Bs[k][tx*8 + 4];
#pragma unroll
            for (int i = 0; i < 8; i++)
#pragma unroll
                for (int j = 0; j < 8; j++)
                    acc[i][j] += a[i] * b[j];
        }
        __syncthreads();
    }
#pragma unroll
    for (int i = 0; i < 8; i++) {
        int row = m0 + ty*8 + i;
#pragma unroll
        for (int j = 0; j < 8; j++)
            C[(size_t)row * N + n0 + tx*8 + j] = acc[i][j] + bias[n0 + tx*8 + j];
    }
}

// ============ RMSNorm (over DIM) + RoPE + transpose to [H][S][D] ===========
__global__ void norm_rope(int which, const float* __restrict__ g,
                          const float* __restrict__ fc, const float* __restrict__ fs)
{
    const float* in = which ? g_Kraw : g_Qraw;
    float* out      = which ? g_k    : g_q;
    int s = blockIdx.x, tid = threadIdx.x;
    const float* row = in + (size_t)s * DM;
    float ss = 0.f;
    for (int i = tid; i < DM; i += 256) { float x = row[i]; ss += x * x; }
#pragma unroll
    for (int o = 16; o > 0; o >>= 1) ss += __shfl_xor_sync(0xffffffffu, ss, o);
    __shared__ float red[8];
    __shared__ float s_rn;
    if ((tid & 31) == 0) red[tid >> 5] = ss;
    __syncthreads();
    if (tid == 0) {
        float t = 0.f;
        for (int i = 0; i < 8; i++) t += red[i];
        s_rn = rsqrtf(t / (float)DM + 1e-6f);
    }
    __syncthreads();
    float rn = s_rn;
    for (int p = tid; p < DM / 2; p += 256) {
        int c = p * 2;
        int h = c >> 7, d = c & 127;          // d even, within head
        float x1 = row[c]     * rn * g[c];
        float x2 = row[c + 1] * rn * g[c + 1];
        float cs = fc[s * HD + d];            // repeated cos
        float sn = fs[s * HD + d + 1];        // repeated sin
        float* op = out + (size_t)h * SQ * HD + (size_t)s * HD + d;
        op[0] = x1 * cs - x2 * sn;
        op[1] = x1 * sn + x2 * cs;
    }
}

// ======================== V: [S][DM] -> [H][S][D] ==========================
__global__ void transpose_v()
{
    int s = blockIdx.x;
    for (int i = threadIdx.x; i < DM; i += 256) {
        int h = i >> 7, d = i & 127;
        g_v[(size_t)h * SQ * HD + (size_t)s * HD + d] = g_Vraw[(size_t)s * DM + i];
    }
}

// ===================== per-(h,s) softmax over D=128 ========================
__global__ void softmax_d(int which)
{
    const float* in = which ? g_k  : g_q;
    float* out      = which ? g_lk : g_lq;
    int b = blockIdx.x;       // h*S + s
    int tid = threadIdx.x;    // 0..127
    float v = in[(size_t)b * HD + tid];
    float m = v;
#pragma unroll
    for (int o = 16; o > 0; o >>= 1) m = fmaxf(m, __shfl_xor_sync(0xffffffffu, m, o));
    __shared__ float sm[4], sd[4];
    int w = tid >> 5, l = tid & 31;
    if (l == 0) sm[w] = m;
    __syncthreads();
    m = fmaxf(fmaxf(sm[0], sm[1]), fmaxf(sm[2], sm[3]));
    float e = expf(v - m);
    float su = e;
#pragma unroll
    for (int o = 16; o > 0; o >>= 1) su += __shfl_xor_sync(0xffffffffu, su, o);
    if (l == 0) sd[w] = su;
    __syncthreads();
    su = sd[0] + sd[1] + sd[2] + sd[3];
    out[(size_t)b * HD + tid] = e / su;
}

// ====================== block means (q: n=128, k: n=64) ====================
__global__ void block_mean(int which)
{
    const float* in = which ? g_k   : g_q;
    float* out      = which ? g_kbm : g_qbm;
    int n  = which ? 64 : 128;
    int nb = which ? NKB : NQB;
    int b = blockIdx.x;             // h*nb + bi
    int h = b / nb, bi = b % nb;
    int d = threadIdx.x;
    const float* p = in + (size_t)h * SQ * HD + (size_t)bi * n * HD + d;
    float s = 0.f;
    for (int r = 0; r < n; r++) s += p[(size_t)r * HD];
    out[(size_t)b * HD + d] = s / (float)n;
}

// ============== block scores + top-7 selection per (h, q-block) ============
__global__ void topk_sel()
{
    int b = blockIdx.x;         // h*NQB + qb
    int h = b >> 4;
    int j = threadIdx.x;        // 0..31 key blocks
    const float* qr = g_qbm + (size_t)b * HD;
    const float* kr = g_kbm + (size_t)(h * NKB + j) * HD;
    float s = 0.f;
    for (int d = 0; d < HD; d++) s += qr[d] * kr[d];
    __shared__ float sc[32];
    sc[j] = s;
    __syncwarp();
    if (j == 0) {
        unsigned used = 0;
        for (int t = 0; t < KSEL; t++) {
            float best = -INFINITY; int bi = 0;
            for (int c = 0; c < 32; c++)
                if (!((used >> c) & 1u) && sc[c] > best) { best = sc[c]; bi = c; }
            used |= 1u << bi;
            g_selbuf[b * 8 + t] = bi;
        }
    }
}

// ============ per (h,kb): Mkv = lk_blkT @ v_blk (128x128), slk =============
#define MKV_SMEM (2 * 64 * HD * 4)
__global__ __launch_bounds__(256) void mkv_kernel()
{
    extern __shared__ float smem[];
    float* lks = smem;                 // [64][128]
    float* vs  = smem + 64 * HD;       // [64][128]
    int b = blockIdx.x;                // h*NKB + kb
    int h = b >> 5;
    int tid = threadIdx.x;
    const float* lkg = g_lk + (size_t)h * SQ * HD + (size_t)(b & 31) * 64 * HD;
    const float* vg  = g_v  + (size_t)h * SQ * HD + (size_t)(b & 31) * 64 * HD;
    for (int i = tid; i < 64 * HD / 4; i += 256) {
        ((float4*)lks)[i] = ((const float4*)lkg)[i];
        ((float4*)vs)[i]  = ((const float4*)vg)[i];
    }
    __syncthreads();
    int tx = tid & 15, ty = tid >> 4;
    int d1 = ty * 8, d2 = tx * 8;
    float acc[8][8] = {};
    for (int r = 0; r < 64; r++) {
        float a[8], bb[8];
#pragma unroll
        for (int i = 0; i < 8; i++) a[i]  = lks[r * HD + d1 + i];
#pragma unroll
        for (int j = 0; j < 8; j++) bb[j] = vs [r * HD + d2 + j];
#pragma unroll
        for (int i = 0; i < 8; i++)
#pragma unroll
            for (int j = 0; j < 8; j++)
                acc[i][j] += a[i] * bb[j];
    }
    float* outp = g_Mkv + (size_t)b * HD * HD;
#pragma unroll
    for (int i = 0; i < 8; i++)
#pragma unroll
        for (int j = 0; j < 8; j++)
            outp[(size_t)(d1 + i) * HD + d2 + j] = acc[i][j];
    if (tid < HD) {
        float sv = 0.f;
        for (int r = 0; r < 64; r++) sv += lks[r * HD + tid];
        g_slk[(size_t)b * HD + tid] = sv;
    }
}

// ================== reductions over the 32 key blocks ======================
__global__ void reduce_mkv()
{
    int idx = blockIdx.x * 256 + threadIdx.x;  // < NH*HD*HD
    int h = idx / (HD * HD);
    int e = idx - h * (HD * HD);
    const float* p = g_Mkv + (size_t)h * NKB * HD * HD + e;
    float s = 0.f;
    for (int kb = 0; kb < NKB; kb++) s += p[(size_t)kb * HD * HD];
    g_sumM[idx] = s;
}
__global__ void reduce_slk()
{
    int h = blockIdx.x, d = threadIdx.x;
    float s = 0.f;
    for (int kb = 0; kb < NKB; kb++) s += g_slk[(size_t)(h * NKB + kb) * HD + d];
    g_sumsl[h * HD + d] = s;
}

// ============================ main attention ================================
// per (h, q-block): sparse online-softmax over 7 selected k-blocks, then
// fold the linear-attention complement via Mkv sums.
#define QP 132
#define KP 132
#define SP 68
#define ATTN_SMEM ((128*QP + 64*KP + 128*SP + 4*128) * 4)

__global__ __launch_bounds__(256) void attn_kernel()
{
    extern __shared__ float smem[];
    float* qs    = smem;                 // [128][QP]
    float* kvs   = qs + 128 * QP;        // [64][KP]
    float* scs   = kvs + 64 * KP;        // [128][SP]
    float* m_s   = scs + 128 * SP;       // [128]
    float* den_s = m_s + 128;            // [128]
    float* fac_s = den_s + 128;          // [128]
    float* slke  = fac_s + 128;          // [128]

    int b = blockIdx.x;
    int h = b >> 4, qb = b & 15;
    int tid = threadIdx.x;
    int tx = tid & 15, ty = tid >> 4;
    int row0 = ty * 8, col0 = tx * 8;

    const float* qg = g_q + (size_t)h * SQ * HD + (size_t)qb * 128 * HD;
    for (int i = tid; i < 128 * HD; i += 256) {
        int r = i >> 7, d = i & 127;
        qs[r * QP + d] = qg[i];
    }
    if (tid < 128) { m_s[tid] = -INFINITY; den_s[tid] = 0.f; }

    float acc[8][8] = {};
    int sel[KSEL];
#pragma unroll
    for (int t = 0; t < KSEL; t++) sel[t] = g_selbuf[b * 8 + t];

    for (int t = 0; t < KSEL; t++) {
        int kb = sel[t];
        const float* kgp = g_k + (size_t)h * SQ * HD + (size_t)kb * 64 * HD;
        __syncthreads();                                   // kvs/scs free
        for (int i = tid; i < 64 * HD; i += 256) {
            int r = i >> 7, d = i & 127;
            kvs[r * KP + d] = kgp[i];
        }
        __syncthreads();
        // scores: 128x64 = q @ k^T * scale  (thread: 8 rows x 4 cols)
        {
            int c0 = tx * 4;
            float sa[8][4] = {};
            for (int d0 = 0; d0 < HD; d0 += 4) {
                float4 a4[8], b4[4];
#pragma unroll
                for (int i = 0; i < 8; i++) a4[i] = *(float4*)&qs[(row0 + i) * QP + d0];
#pragma unroll
                for (int j = 0; j < 4; j++) b4[j] = *(float4*)&kvs[(c0 + j) * KP + d0];
#pragma unroll
                for (int i = 0; i < 8; i++)
#pragma unroll
                    for (int j = 0; j < 4; j++)
                        sa[i][j] += a4[i].x * b4[j].x + a4[i].y * b4[j].y
                                  + a4[i].z * b4[j].z + a4[i].w * b4[j].w;
            }
#pragma unroll
            for (int i = 0; i < 8; i++)
#pragma unroll
                for (int j = 0; j < 4; j++)
                    scs[(row0 + i) * SP + c0 + j] = sa[i][j] * ATT_SCALE;
        }
        __syncthreads();
        // load V (all threads) + row stats (128 threads, disjoint smem)
        const float* vgp = g_v + (size_t)h * SQ * HD + (size_t)kb * 64 * HD;
        for (int i = tid; i < 64 * HD; i += 256) {
            int r = i >> 7, d = i & 127;
            kvs[r * KP + d] = vgp[i];
        }
        if (tid < 128) {
            int r = tid;
            float mold = m_s[r], mx = mold;
            for (int c = 0; c < 64; c++) mx = fmaxf(mx, scs[r * SP + c]);
            float f = expf(mold - mx);   // -inf -> 0 on first block
            float ds = 0.f;
            for (int c = 0; c < 64; c++) {
                float pv = expf(scs[r * SP + c] - mx);
                scs[r * SP + c] = pv;
                ds += pv;
            }
            den_s[r] = den_s[r] * f + ds;
            m_s[r] = mx;
            fac_s[r] = f;
        }
        __syncthreads();
        // rescale accumulator + P @ V
#pragma unroll
        for (int i = 0; i < 8; i++) {
            float f = fac_s[row0 + i];
#pragma unroll
            for (int j = 0; j < 8; j++) acc[i][j] *= f;
        }
        for (int r0 = 0; r0 < 64; r0 += 4) {
            float p[8][4];
#pragma unroll
            for (int i = 0; i < 8; i++) {
                float4 t4 = *(float4*)&scs[(row0 + i) * SP + r0];
                p[i][0] = t4.x; p[i][1] = t4.y; p[i][2] = t4.z; p[i][3] = t4.w;
            }
#pragma unroll
            for (int x = 0; x < 4; x++) {
                float4 v0 = *(float4*)&kvs[(r0 + x) * KP + col0];
                float4 v1 = *(float4*)&kvs[(r0 + x) * KP + col0 + 4];
#pragma unroll
                for (int i = 0; i < 8; i++) {
                    float pp = p[i][x];
                    acc[i][0] += pp * v0.x; acc[i][1] += pp * v0.y;
                    acc[i][2] += pp * v0.z; acc[i][3] += pp * v0.w;
                    acc[i][4] += pp * v1.x; acc[i][5] += pp * v1.y;
                    acc[i][6] += pp * v1.z; acc[i][7] += pp * v1.w;
                }
            }
        }
    }
    __syncthreads();

    // ---- linear-attention complement: acc += (w*lq) @ KVexcl ----
    if (tid < 128) {
        float s = g_sumsl[h * HD + tid];
#pragma unroll
        for (int t = 0; t < KSEL; t++)
            s -= g_slk[(size_t)(h * NKB + sel[t]) * HD + tid];
        slke[tid] = s;
    }
    const float* lqp = g_lq + (size_t)h * SQ * HD + (size_t)qb * 128 * HD;
    for (int i = tid; i < 128 * HD; i += 256) {
        int r = i >> 7, d = i & 127;
        qs[r * QP + d] = lqp[i] * expf(-m_s[r]);     // fold w = exp(-m)
    }
    __syncthreads();
    if (tid < 128) {    // den += w * den_l  (w already folded into qs rows)
        int r = tid;
        float dl = 0.f;
        for (int d = 0; d < HD; d++) dl += qs[r * QP + d] * slke[d];
        den_s[r] += dl;
    }
    for (int c0 = 0; c0 < HD; c0 += 64) {
        for (int i = tid; i < 64 * HD; i += 256) {
            int dd = i >> 7, d2 = i & 127;
            float s = g_sumM[((size_t)h * HD + c0 + dd) * HD + d2];
#pragma unroll
            for (int t = 0; t < KSEL; t++)
                s -= g_Mkv[(((size_t)h * NKB + sel[t]) * HD + c0 + dd) * HD + d2];
            kvs[dd * KP + d2] = s;
        }
        __syncthreads();
        for (int r0 = 0; r0 < 64; r0 += 4) {
            float a[8][4];
#pragma unroll
            for (int i = 0; i < 8; i++) {
                float4 t4 = *(float4*)&qs[(row0 + i) * QP + c0 + r0];
                a[i][0] = t4.x; a[i][1] = t4.y; a[i][2] = t4.z; a[i][3] = t4.w;
            }
#pragma unroll
            for (int x = 0; x < 4; x++) {
                float4 v0 = *(float4*)&kvs[(r0 + x) * KP + col0];
                float4 v1 = *(float4*)&kvs[(r0 + x) * KP + col0 + 4];
#pragma unroll
                for (int i = 0; i < 8; i++) {
                    float pp = a[i][x];
                    acc[i][0] += pp * v0.x; acc[i][1] += pp * v0.y;
                    acc[i][2] += pp * v0.z; acc[i][3] += pp * v0.w;
                    acc[i][4] += pp * v1.x; acc[i][5] += pp * v1.y;
                    acc[i][6] += pp * v1.z; acc[i][7] += pp * v1.w;
                }
            }
        }
        __syncthreads();
    }
    // output in [S][DM] layout (ready for the Wo GEMM)
#pragma unroll
    for (int i = 0; i < 8; i++) {
        int r = row0 + i;
        float inv = 1.f / den_s[r];
        float* op = g_O + (size_t)(qb * 128 + r) * DM + h * HD + col0;
#pragma unroll
        for (int j = 0; j < 8; j++) op[j] = acc[i][j] * inv;
    }
}

// ================================ launcher =================================
extern "C" void kernel_launch(void* const* d_in, const int* in_sizes, int n_in,
                              void* d_out, int out_size)
{
    const float* hs = (const float*)d_in[0];
    const float* fc = (const float*)d_in[1];
    const float* fs = (const float*)d_in[2];
    const float* Wq = (const float*)d_in[3];
    const float* bq = (const float*)d_in[4];
    const float* Wk = (const float*)d_in[5];
    const float* bk = (const float*)d_in[6];
    const float* Wv = (const float*)d_in[7];
    const float* bv = (const float*)d_in[8];
    const float* Wo = (const float*)d_in[9];
    const float* bo = (const float*)d_in[10];
    const float* gq = (const float*)d_in[11];
    const float* gk = (const float*)d_in[12];
    float* out = (float*)d_out;

    float *Qraw, *Kraw, *Vraw, *O;
    cudaGetSymbolAddress((void**)&Qraw, g_Qraw);
    cudaGetSymbolAddress((void**)&Kraw, g_Kraw);
    cudaGetSymbolAddress((void**)&Vraw, g_Vraw);
    cudaGetSymbolAddress((void**)&O,    g_O);

    cudaFuncSetAttribute(mkv_kernel,  cudaFuncAttributeMaxDynamicSharedMemorySize, MKV_SMEM);
    cudaFuncSetAttribute(attn_kernel, cudaFuncAttributeMaxDynamicSharedMemorySize, ATTN_SMEM);

    dim3 gg(DM / 128, SQ / 128);
    sgemm_bias<<<gg, 256>>>(hs, Wq, bq, Qraw, SQ, DM, DM);
    sgemm_bias<<<gg, 256>>>(hs, Wk, bk, Kraw, SQ, DM, DM);
    sgemm_bias<<<gg, 256>>>(hs, Wv, bv, Vraw, SQ, DM, DM);
    norm_rope<<<SQ, 256>>>(0, gq, fc, fs);
    norm_rope<<<SQ, 256>>>(1, gk, fc, fs);
    transpose_v<<<SQ, 256>>>();
    softmax_d<<<NH * SQ, 128>>>(0);
    softmax_d<<<NH * SQ, 128>>>(1);
    block_mean<<<NH * NQB, 128>>>(0);
    block_mean<<<NH * NKB, 128>>>(1);
    topk_sel<<<NH * NQB, 32>>>();
    mkv_kernel<<<NH * NKB, 256, MKV_SMEM>>>();
    reduce_mkv<<<NH * HD * HD / 256, 256>>>();
    reduce_slk<<<NH, 128>>>();
    attn_kernel<<<NH * NQB, 256, ATTN_SMEM>>>();
    sgemm_bias<<<gg, 256>>>(O, Wo, bo, out, SQ, DM, DM);
}